// round 3
// baseline (speedup 1.0000x reference)
#include <cuda_runtime.h>
#include <cuda_bf16.h>
#include <stdint.h>

// Problem dims (fixed by the dataset)
#define NBATCH 4
#define NROWS  8192
#define DMEM   128
#define NTILES 64           // 8192 / 128 j-tiles
#define JSPLIT 4
#define NJ     (NTILES / JSPLIT)
#define TILE8  16384        // 128 rows * 128 fp8 bytes
#define THRESH 0.65f

// Scratch (device globals are the sanctioned scratch mechanism)
__device__ __align__(16) uint8_t       g_proj[(size_t)NBATCH * NROWS * DMEM];  // 4 MB e4m3 normalized proj
__device__ __align__(16) __nv_bfloat16 g_xb[(size_t)NBATCH * NROWS * DMEM];    // 8 MB bf16 X
__device__ __align__(16) __nv_bfloat16 g_wb[DMEM * DMEM];                      // 32 KB bf16 W
__device__ float g_deg[NBATCH * NROWS];

// ---------------------------------------------------------------------------
// helpers
// ---------------------------------------------------------------------------
__device__ __forceinline__ uint32_t su32(const void* p) {
    uint32_t a;
    asm("{ .reg .u64 t; cvta.to.shared.u64 t, %1; cvt.u32.u64 %0, t; }" : "=r"(a) : "l"(p));
    return a;
}

#define LDMATRIX_X4(r0, r1, r2, r3, addr) \
    asm volatile("ldmatrix.sync.aligned.m8n8.x4.shared.b16 {%0,%1,%2,%3}, [%4];" \
                 : "=r"(r0), "=r"(r1), "=r"(r2), "=r"(r3) : "r"(addr))

#define MMA_BF16(d, a, b0, b1) \
    asm volatile("mma.sync.aligned.m16n8k16.row.col.f32.bf16.bf16.f32 " \
                 "{%0,%1,%2,%3}, {%4,%5,%6,%7}, {%8,%9}, {%0,%1,%2,%3};" \
                 : "+f"((d)[0]), "+f"((d)[1]), "+f"((d)[2]), "+f"((d)[3]) \
                 : "r"((a)[0]), "r"((a)[1]), "r"((a)[2]), "r"((a)[3]), "r"(b0), "r"(b1))

#define MMA_FP8(d, a, b0, b1) \
    asm volatile("mma.sync.aligned.m16n8k32.row.col.f32.e4m3.e4m3.f32 " \
                 "{%0,%1,%2,%3}, {%4,%5,%6,%7}, {%8,%9}, {%0,%1,%2,%3};" \
                 : "+f"((d)[0]), "+f"((d)[1]), "+f"((d)[2]), "+f"((d)[3]) \
                 : "r"((a)[0]), "r"((a)[1]), "r"((a)[2]), "r"((a)[3]), "r"(b0), "r"(b1))

// bf16 128x128 tile (32KB, 256B rows, 16 chunks/row, c^(r&7) swizzle). 256 thr.
__device__ __forceinline__ void copy_tile16(uint32_t dst, const __nv_bfloat16* src, int tid) {
    #pragma unroll
    for (int k = 0; k < 8; k++) {
        int idx = tid + k * 256;
        int r = idx >> 4, c = idx & 15;
        uint32_t doff = (uint32_t)(r * 256 + ((c ^ (r & 7)) << 4));
        asm volatile("cp.async.cg.shared.global [%0], [%1], 16;"
                     :: "r"(dst + doff), "l"((const char*)src + (size_t)idx * 16) : "memory");
    }
}

// fp8 128x128 tile (16KB, 128B rows, 8 chunks/row, c^(r&7) swizzle). 256 thr.
__device__ __forceinline__ void copy_tile8(uint32_t dst, const uint8_t* src, int tid) {
    #pragma unroll
    for (int k = 0; k < 4; k++) {
        int idx = tid + k * 256;
        int r = idx >> 3, c = idx & 7;
        uint32_t doff = (uint32_t)(r * 128 + ((c ^ (r & 7)) << 4));
        asm volatile("cp.async.cg.shared.global [%0], [%1], 16;"
                     :: "r"(dst + doff), "l"((const char*)src + (size_t)idx * 16) : "memory");
    }
}

// ---------------------------------------------------------------------------
// Stage 0: X,W -> bf16 scratch; zero g_deg
// ---------------------------------------------------------------------------
__global__ void __launch_bounds__(256) prep_kernel(const float* __restrict__ X,
                                                   const float* __restrict__ W) {
    int b = blockIdx.x, tid = threadIdx.x;
    if (b < 2048) {                                    // X: 4.19M floats, 8/thread
        size_t g = ((size_t)b * 256 + tid) * 2;        // float4 index
        float4 a0 = reinterpret_cast<const float4*>(X)[g];
        float4 a1 = reinterpret_cast<const float4*>(X)[g + 1];
        __nv_bfloat162 h0 = __floats2bfloat162_rn(a0.x, a0.y);
        __nv_bfloat162 h1 = __floats2bfloat162_rn(a0.z, a0.w);
        __nv_bfloat162 h2 = __floats2bfloat162_rn(a1.x, a1.y);
        __nv_bfloat162 h3 = __floats2bfloat162_rn(a1.z, a1.w);
        reinterpret_cast<uint4*>(g_xb)[g / 2] =
            make_uint4(*(uint32_t*)&h0, *(uint32_t*)&h1, *(uint32_t*)&h2, *(uint32_t*)&h3);
    } else if (b < 2056) {                             // W: 16384 floats
        size_t g = ((size_t)(b - 2048) * 256 + tid) * 2;
        float4 a0 = reinterpret_cast<const float4*>(W)[g];
        float4 a1 = reinterpret_cast<const float4*>(W)[g + 1];
        __nv_bfloat162 h0 = __floats2bfloat162_rn(a0.x, a0.y);
        __nv_bfloat162 h1 = __floats2bfloat162_rn(a0.z, a0.w);
        __nv_bfloat162 h2 = __floats2bfloat162_rn(a1.x, a1.y);
        __nv_bfloat162 h3 = __floats2bfloat162_rn(a1.z, a1.w);
        reinterpret_cast<uint4*>(g_wb)[g / 2] =
            make_uint4(*(uint32_t*)&h0, *(uint32_t*)&h1, *(uint32_t*)&h2, *(uint32_t*)&h3);
    } else {                                           // zero g_deg: 32768 floats
        size_t g = ((size_t)(b - 2056) * 256 + tid) * 2;
        reinterpret_cast<float4*>(g_deg)[g]     = make_float4(0.f, 0.f, 0.f, 0.f);
        reinterpret_cast<float4*>(g_deg)[g + 1] = make_float4(0.f, 0.f, 0.f, 0.f);
    }
}

// ---------------------------------------------------------------------------
// Stage 1: proj = normalize(Xb @ Wb^T + b) -> e4m3, via bf16 mma.sync.
// CTA: 256 thr, 8 warps; warp w owns rows w*16..+15, full n=128 (16 n8-frags).
// ---------------------------------------------------------------------------
__global__ void __launch_bounds__(256) proj_kernel(const float* __restrict__ Bv) {
    extern __shared__ unsigned char dsm[];
    uint32_t smX = su32(dsm);            // 32 KB
    uint32_t smW = smX + 32768;          // 32 KB
    float* bs = (float*)(dsm + 65536);   // 512 B

    int tid = threadIdx.x, w = tid >> 5, l = tid & 31;
    int r0 = blockIdx.x * 128;

    copy_tile16(smX, g_xb + (size_t)r0 * DMEM, tid);
    copy_tile16(smW, g_wb, tid);
    asm volatile("cp.async.commit_group;" ::: "memory");
    if (tid < 128) bs[tid] = Bv[tid];
    asm volatile("cp.async.wait_group 0;" ::: "memory");
    __syncthreads();

    float acc[16][4];
    #pragma unroll
    for (int f = 0; f < 16; f++)
        #pragma unroll
        for (int p = 0; p < 4; p++) acc[f][p] = 0.f;

    #pragma unroll
    for (int k = 0; k < 8; k++) {
        uint32_t a[4];
        {
            int r = w * 16 + (l & 15);
            int chunk = k * 2 + ((l >> 4) & 1);
            uint32_t addr = smX + r * 256 + ((chunk ^ (r & 7)) << 4);
            LDMATRIX_X4(a[0], a[1], a[2], a[3], addr);
        }
        #pragma unroll
        for (int nf = 0; nf < 8; nf++) {
            int nn = nf * 16 + (l & 7) + ((l & 16) ? 8 : 0);
            int chunk = k * 2 + ((l >> 3) & 1);
            uint32_t addr = smW + nn * 256 + ((chunk ^ (nn & 7)) << 4);
            uint32_t b0, b1, b2, b3;
            LDMATRIX_X4(b0, b1, b2, b3, addr);
            MMA_BF16(acc[nf * 2],     a, b0, b1);
            MMA_BF16(acc[nf * 2 + 1], a, b2, b3);
        }
    }

    // bias + row sums of squares (rows l/4 and l/4+8 of this warp's m16)
    float slo = 0.f, shi = 0.f;
    #pragma unroll
    for (int f = 0; f < 16; f++) {
        int c0 = f * 8 + 2 * (l & 3);
        float b0 = bs[c0], b1 = bs[c0 + 1];
        acc[f][0] += b0; acc[f][1] += b1;
        acc[f][2] += b0; acc[f][3] += b1;
        slo += acc[f][0] * acc[f][0] + acc[f][1] * acc[f][1];
        shi += acc[f][2] * acc[f][2] + acc[f][3] * acc[f][3];
    }
    slo += __shfl_xor_sync(0xffffffffu, slo, 1);
    slo += __shfl_xor_sync(0xffffffffu, slo, 2);
    shi += __shfl_xor_sync(0xffffffffu, shi, 1);
    shi += __shfl_xor_sync(0xffffffffu, shi, 2);
    float rlo = rsqrtf(fmaxf(slo, 1e-24f));
    float rhi = rsqrtf(fmaxf(shi, 1e-24f));

    int rowlo = r0 + w * 16 + (l >> 2);
    #pragma unroll
    for (int f = 0; f < 16; f++) {
        int c0 = f * 8 + 2 * (l & 3);
        uint16_t plo, phi;
        asm("cvt.rn.satfinite.e4m3x2.f32 %0, %1, %2;"
            : "=h"(plo) : "f"(acc[f][1] * rlo), "f"(acc[f][0] * rlo));
        asm("cvt.rn.satfinite.e4m3x2.f32 %0, %1, %2;"
            : "=h"(phi) : "f"(acc[f][3] * rhi), "f"(acc[f][2] * rhi));
        *reinterpret_cast<uint16_t*>(g_proj + (size_t)rowlo * DMEM + c0)       = plo;
        *reinterpret_cast<uint16_t*>(g_proj + (size_t)(rowlo + 8) * DMEM + c0) = phi;
    }
}

// ---------------------------------------------------------------------------
// Stage 2: sim = P P^T per 128x128 tile via fp8 mma.sync; threshold in regs.
// CTA: 256 thr = 4 m-warps x 2 n-halves. Hits (~zero) handled atomically.
// ---------------------------------------------------------------------------
__global__ void __launch_bounds__(256, 2) sim_kernel(const float* __restrict__ X,
                                                     float* __restrict__ out) {
    extern __shared__ unsigned char dsm[];
    uint32_t smA  = su32(dsm);
    uint32_t smB0 = smA + TILE8;
    uint32_t smB1 = smA + 2 * TILE8;

    int tid = threadIdx.x, wid = tid >> 5, l = tid & 31;
    int wm = wid >> 1, wn = wid & 1;

    int bid = blockIdx.x;
    int batch = bid >> 8;
    int it    = (bid >> 2) & 63;
    int j0    = (bid & 3) * NJ;

    const uint8_t* pb = g_proj + (size_t)batch * NROWS * DMEM;
    const float* Xb = X + (size_t)batch * NROWS * DMEM;
    float* outb = out + (size_t)batch * NROWS * DMEM;
    float* degb = g_deg + batch * NROWS;

    copy_tile8(smA, pb + (size_t)it * 128 * DMEM, tid);
    copy_tile8(smB0, pb + (size_t)j0 * 128 * DMEM, tid);
    asm volatile("cp.async.commit_group;" ::: "memory");
    copy_tile8(smB1, pb + (size_t)(j0 + 1) * 128 * DMEM, tid);
    asm volatile("cp.async.commit_group;" ::: "memory");
    asm volatile("cp.async.wait_group 1;" ::: "memory");
    __syncthreads();

    // Resident A fragments: 2 m16-frags x 4 k32-steps x 4 regs = 32 regs
    uint32_t a[2][4][4];
    #pragma unroll
    for (int m = 0; m < 2; m++)
        #pragma unroll
        for (int k = 0; k < 4; k++) {
            int r = wm * 32 + m * 16 + (l & 15);
            int chunk = k * 2 + ((l >> 4) & 1);
            uint32_t addr = smA + r * 128 + ((chunk ^ (r & 7)) << 4);
            LDMATRIX_X4(a[m][k][0], a[m][k][1], a[m][k][2], a[m][k][3], addr);
        }

    for (int jt = j0; jt < j0 + NJ; jt++) {
        uint32_t smB = ((jt - j0) & 1) ? smB1 : smB0;

        #pragma unroll 1
        for (int g = 0; g < 4; g++) {
            int n0 = wn * 64 + g * 16;
            float d[2][2][4];
            #pragma unroll
            for (int m = 0; m < 2; m++)
                #pragma unroll
                for (int h = 0; h < 2; h++)
                    #pragma unroll
                    for (int p = 0; p < 4; p++) d[m][h][p] = 0.f;

            #pragma unroll
            for (int k = 0; k < 4; k++) {
                int nn = n0 + (l & 7) + ((l & 16) ? 8 : 0);
                int chunk = k * 2 + ((l >> 3) & 1);
                uint32_t addr = smB + nn * 128 + ((chunk ^ (nn & 7)) << 4);
                uint32_t b0, b1, b2, b3;
                LDMATRIX_X4(b0, b1, b2, b3, addr);
                #pragma unroll
                for (int m = 0; m < 2; m++) {
                    MMA_FP8(d[m][0], a[m][k], b0, b1);
                    MMA_FP8(d[m][1], a[m][k], b2, b3);
                }
            }

            float vmax = d[0][0][0];
            #pragma unroll
            for (int m = 0; m < 2; m++)
                #pragma unroll
                for (int h = 0; h < 2; h++)
                    #pragma unroll
                    for (int p = 0; p < 4; p++) vmax = fmaxf(vmax, d[m][h][p]);
            unsigned warp_any = __ballot_sync(0xffffffffu, vmax > THRESH);

            if (warp_any) {   // rare: diagonal (skipped) or a true hit
                #pragma unroll
                for (int m = 0; m < 2; m++)
                    #pragma unroll
                    for (int h = 0; h < 2; h++)
                        #pragma unroll
                        for (int p = 0; p < 4; p++) {
                            unsigned msk = __ballot_sync(0xffffffffu, d[m][h][p] > THRESH);
                            while (msk) {
                                int b = __ffs(msk) - 1; msk &= msk - 1;
                                int ib = it * 128 + wm * 32 + m * 16 + (b >> 2) + ((p & 2) ? 8 : 0);
                                int jb = jt * 128 + n0 + h * 8 + ((b & 3) << 1) + (p & 1);
                                if (ib != jb) {
                                    float4 xv = reinterpret_cast<const float4*>(Xb + (size_t)jb * DMEM)[l];
                                    float* orow = outb + (size_t)ib * DMEM + l * 4;
                                    atomicAdd(orow + 0, xv.x);
                                    atomicAdd(orow + 1, xv.y);
                                    atomicAdd(orow + 2, xv.z);
                                    atomicAdd(orow + 3, xv.w);
                                    if (l == 0) atomicAdd(&degb[ib], 1.0f);
                                }
                            }
                        }
            }
        }

        __syncthreads();
        if (jt + 2 < j0 + NJ)
            copy_tile8(smB, pb + (size_t)(jt + 2) * 128 * DMEM, tid);
        asm volatile("cp.async.commit_group;" ::: "memory");
        asm volatile("cp.async.wait_group 1;" ::: "memory");
        __syncthreads();
    }
}

// ---------------------------------------------------------------------------
// Stage 3: out[i] = (hits[i] + X[i]) / (1 + deg_hits[i])
// ---------------------------------------------------------------------------
__global__ void __launch_bounds__(256) fin_kernel(const float* __restrict__ X,
                                                  float* __restrict__ out) {
    size_t v = (size_t)blockIdx.x * 256 + threadIdx.x;
    int row = (int)(v >> 5);
    float inv = 1.0f / (1.0f + g_deg[row]);
    float4 o = reinterpret_cast<float4*>(out)[v];
    float4 x = reinterpret_cast<const float4*>(X)[v];
    o.x = (o.x + x.x) * inv; o.y = (o.y + x.y) * inv;
    o.z = (o.z + x.z) * inv; o.w = (o.w + x.w) * inv;
    reinterpret_cast<float4*>(out)[v] = o;
}

// ---------------------------------------------------------------------------
extern "C" void kernel_launch(void* const* d_in, const int* in_sizes, int n_in,
                              void* d_out, int out_size) {
    (void)in_sizes; (void)n_in; (void)out_size;
    const float* X  = (const float*)d_in[0];
    const float* W  = (const float*)d_in[1];
    const float* Bv = (const float*)d_in[2];
    float* out = (float*)d_out;

    const int PROJ_SMEM = 65536 + 512;
    const int SIM_SMEM  = 3 * TILE8;     // 48 KB
    cudaFuncSetAttribute(proj_kernel, cudaFuncAttributeMaxDynamicSharedMemorySize, PROJ_SMEM);
    cudaFuncSetAttribute(sim_kernel,  cudaFuncAttributeMaxDynamicSharedMemorySize, SIM_SMEM);

    cudaMemsetAsync(d_out, 0, sizeof(float) * (size_t)NBATCH * NROWS * DMEM, 0);

    prep_kernel<<<2072, 256>>>(X, W);
    proj_kernel<<<(NBATCH * NROWS) / 128, 256, PROJ_SMEM>>>(Bv);
    sim_kernel<<<NBATCH * 64 * JSPLIT, 256, SIM_SMEM>>>(X, out);
    fin_kernel<<<(NBATCH * NROWS * DMEM / 4) / 256, 256>>>(X, out);
}

// round 4
// speedup vs baseline: 1.7899x; 1.7899x over previous
#include <cuda_runtime.h>
#include <cuda_bf16.h>
#include <stdint.h>

// Problem dims (fixed by the dataset)
#define NBATCH 4
#define NROWS  8192
#define DMEM   128
#define NTILES 64
#define TILEB  32768        // 128 rows * 128 bf16 * 2B
#define THRESH 0.65f

// Scratch (device globals are the sanctioned scratch mechanism)
__device__ __align__(16) __nv_bfloat16 g_proj[(size_t)NBATCH * NROWS * DMEM]; // 8 MB normalized proj
__device__ __align__(16) __nv_bfloat16 g_xb[(size_t)NBATCH * NROWS * DMEM];   // 8 MB bf16 X
__device__ __align__(16) __nv_bfloat16 g_wb[DMEM * DMEM];                     // 32 KB bf16 W
__device__ float g_deg[NBATCH * NROWS];

// ---------------------------------------------------------------------------
// helpers
// ---------------------------------------------------------------------------
__device__ __forceinline__ uint32_t su32(const void* p) {
    uint32_t a;
    asm("{ .reg .u64 t; cvta.to.shared.u64 t, %1; cvt.u32.u64 %0, t; }" : "=r"(a) : "l"(p));
    return a;
}

#define LDMATRIX_X4(r0, r1, r2, r3, addr) \
    asm volatile("ldmatrix.sync.aligned.m8n8.x4.shared.b16 {%0,%1,%2,%3}, [%4];" \
                 : "=r"(r0), "=r"(r1), "=r"(r2), "=r"(r3) : "r"(addr))

#define MMA_BF16(d, a, b0, b1) \
    asm volatile("mma.sync.aligned.m16n8k16.row.col.f32.bf16.bf16.f32 " \
                 "{%0,%1,%2,%3}, {%4,%5,%6,%7}, {%8,%9}, {%0,%1,%2,%3};" \
                 : "+f"((d)[0]), "+f"((d)[1]), "+f"((d)[2]), "+f"((d)[3]) \
                 : "r"((a)[0]), "r"((a)[1]), "r"((a)[2]), "r"((a)[3]), "r"(b0), "r"(b1))

// bf16 128x128 tile (32KB, 256B rows, 16 chunks/row, c^(r&7) swizzle). 256 thr.
__device__ __forceinline__ void copy_tile16(uint32_t dst, const __nv_bfloat16* src, int tid) {
    #pragma unroll
    for (int k = 0; k < 8; k++) {
        int idx = tid + k * 256;
        int r = idx >> 4, c = idx & 15;
        uint32_t doff = (uint32_t)(r * 256 + ((c ^ (r & 7)) << 4));
        asm volatile("cp.async.cg.shared.global [%0], [%1], 16;"
                     :: "r"(dst + doff), "l"((const char*)src + (size_t)idx * 16) : "memory");
    }
}

// Load this warp's resident A fragments (m32 x k128) from smA.
__device__ __forceinline__ void load_afrags(uint32_t a[2][8][4], uint32_t smA, int wm, int l) {
    #pragma unroll
    for (int m = 0; m < 2; m++)
        #pragma unroll
        for (int k = 0; k < 8; k++) {
            int r = wm * 32 + m * 16 + (l & 15);
            int chunk = k * 2 + ((l >> 4) & 1);
            uint32_t addr = smA + r * 256 + ((chunk ^ (r & 7)) << 4);
            LDMATRIX_X4(a[m][k][0], a[m][k][1], a[m][k][2], a[m][k][3], addr);
        }
}

// ---------------------------------------------------------------------------
// Stage 0: X,W -> bf16 scratch; out = X (analytic diagonal term); zero g_deg
// ---------------------------------------------------------------------------
__global__ void __launch_bounds__(256) prep_kernel(const float* __restrict__ X,
                                                   const float* __restrict__ W,
                                                   float* __restrict__ out) {
    int b = blockIdx.x, tid = threadIdx.x;
    if (b < 2048) {                                    // X -> bf16, and out = X
        size_t g = ((size_t)b * 256 + tid) * 2;        // float4 index
        float4 a0 = reinterpret_cast<const float4*>(X)[g];
        float4 a1 = reinterpret_cast<const float4*>(X)[g + 1];
        reinterpret_cast<float4*>(out)[g]     = a0;
        reinterpret_cast<float4*>(out)[g + 1] = a1;
        __nv_bfloat162 h0 = __floats2bfloat162_rn(a0.x, a0.y);
        __nv_bfloat162 h1 = __floats2bfloat162_rn(a0.z, a0.w);
        __nv_bfloat162 h2 = __floats2bfloat162_rn(a1.x, a1.y);
        __nv_bfloat162 h3 = __floats2bfloat162_rn(a1.z, a1.w);
        reinterpret_cast<uint4*>(g_xb)[g / 2] =
            make_uint4(*(uint32_t*)&h0, *(uint32_t*)&h1, *(uint32_t*)&h2, *(uint32_t*)&h3);
    } else if (b < 2056) {                             // W -> bf16
        size_t g = ((size_t)(b - 2048) * 256 + tid) * 2;
        float4 a0 = reinterpret_cast<const float4*>(W)[g];
        float4 a1 = reinterpret_cast<const float4*>(W)[g + 1];
        __nv_bfloat162 h0 = __floats2bfloat162_rn(a0.x, a0.y);
        __nv_bfloat162 h1 = __floats2bfloat162_rn(a0.z, a0.w);
        __nv_bfloat162 h2 = __floats2bfloat162_rn(a1.x, a1.y);
        __nv_bfloat162 h3 = __floats2bfloat162_rn(a1.z, a1.w);
        reinterpret_cast<uint4*>(g_wb)[g / 2] =
            make_uint4(*(uint32_t*)&h0, *(uint32_t*)&h1, *(uint32_t*)&h2, *(uint32_t*)&h3);
    } else {                                           // zero g_deg
        size_t g = ((size_t)(b - 2056) * 256 + tid) * 2;
        reinterpret_cast<float4*>(g_deg)[g]     = make_float4(0.f, 0.f, 0.f, 0.f);
        reinterpret_cast<float4*>(g_deg)[g + 1] = make_float4(0.f, 0.f, 0.f, 0.f);
    }
}

// ---------------------------------------------------------------------------
// Stage 1: proj = normalize(Xb @ Wb^T + b) -> bf16 row-major, via bf16 mma.
// CTA: 256 thr, 8 warps; warp w owns rows w*16..+15, full n=128.
// ---------------------------------------------------------------------------
__global__ void __launch_bounds__(256) proj_kernel(const float* __restrict__ Bv) {
    extern __shared__ unsigned char dsm[];
    uint32_t smX = su32(dsm);            // 32 KB
    uint32_t smW = smX + 32768;          // 32 KB
    float* bs = (float*)(dsm + 65536);   // 512 B

    int tid = threadIdx.x, w = tid >> 5, l = tid & 31;
    int r0 = blockIdx.x * 128;

    copy_tile16(smX, g_xb + (size_t)r0 * DMEM, tid);
    copy_tile16(smW, g_wb, tid);
    asm volatile("cp.async.commit_group;" ::: "memory");
    if (tid < 128) bs[tid] = Bv[tid];
    asm volatile("cp.async.wait_group 0;" ::: "memory");
    __syncthreads();

    float acc[16][4];
    #pragma unroll
    for (int f = 0; f < 16; f++)
        #pragma unroll
        for (int p = 0; p < 4; p++) acc[f][p] = 0.f;

    #pragma unroll
    for (int k = 0; k < 8; k++) {
        uint32_t a[4];
        {
            int r = w * 16 + (l & 15);
            int chunk = k * 2 + ((l >> 4) & 1);
            uint32_t addr = smX + r * 256 + ((chunk ^ (r & 7)) << 4);
            LDMATRIX_X4(a[0], a[1], a[2], a[3], addr);
        }
        #pragma unroll
        for (int nf = 0; nf < 8; nf++) {
            int nn = nf * 16 + (l & 7) + ((l & 16) ? 8 : 0);
            int chunk = k * 2 + ((l >> 3) & 1);
            uint32_t addr = smW + nn * 256 + ((chunk ^ (nn & 7)) << 4);
            uint32_t b0, b1, b2, b3;
            LDMATRIX_X4(b0, b1, b2, b3, addr);
            MMA_BF16(acc[nf * 2],     a, b0, b1);
            MMA_BF16(acc[nf * 2 + 1], a, b2, b3);
        }
    }

    // bias + row sums of squares (rows l/4 and l/4+8 of this warp's m16)
    float slo = 0.f, shi = 0.f;
    #pragma unroll
    for (int f = 0; f < 16; f++) {
        int c0 = f * 8 + 2 * (l & 3);
        float b0 = bs[c0], b1 = bs[c0 + 1];
        acc[f][0] += b0; acc[f][1] += b1;
        acc[f][2] += b0; acc[f][3] += b1;
        slo += acc[f][0] * acc[f][0] + acc[f][1] * acc[f][1];
        shi += acc[f][2] * acc[f][2] + acc[f][3] * acc[f][3];
    }
    slo += __shfl_xor_sync(0xffffffffu, slo, 1);
    slo += __shfl_xor_sync(0xffffffffu, slo, 2);
    shi += __shfl_xor_sync(0xffffffffu, shi, 1);
    shi += __shfl_xor_sync(0xffffffffu, shi, 2);
    float rlo = rsqrtf(fmaxf(slo, 1e-24f));
    float rhi = rsqrtf(fmaxf(shi, 1e-24f));

    int rowlo = r0 + w * 16 + (l >> 2);
    #pragma unroll
    for (int f = 0; f < 16; f++) {
        int c0 = f * 8 + 2 * (l & 3);
        __nv_bfloat162 hlo = __floats2bfloat162_rn(acc[f][0] * rlo, acc[f][1] * rlo);
        __nv_bfloat162 hhi = __floats2bfloat162_rn(acc[f][2] * rhi, acc[f][3] * rhi);
        *reinterpret_cast<uint32_t*>(g_proj + (size_t)rowlo * DMEM + c0)       = *(uint32_t*)&hlo;
        *reinterpret_cast<uint32_t*>(g_proj + (size_t)(rowlo + 8) * DMEM + c0) = *(uint32_t*)&hhi;
    }
}

// ---------------------------------------------------------------------------
// Stage 2: upper-triangular sim tiles (jt >= it) via bf16 mma.sync.
// CTA = (batch, pair p, quarter q). Pair p covers row p (j=p..63) then row
// 63-p (j=63-p..63): 65 tiles, split x4. Symmetric hits applied both ways.
// ---------------------------------------------------------------------------
__global__ void __launch_bounds__(256, 2) sim_kernel(const float* __restrict__ X,
                                                     float* __restrict__ out) {
    extern __shared__ unsigned char dsm[];
    uint32_t smA  = su32(dsm);
    uint32_t smB0 = smA + TILEB;
    uint32_t smB1 = smA + 2 * TILEB;

    int tid = threadIdx.x, wid = tid >> 5, l = tid & 31;
    int wm = wid >> 1, wn = wid & 1;

    int bid = blockIdx.x;
    int batch = bid >> 7;
    int p     = (bid >> 2) & 31;
    int q     = bid & 3;
    int n0    = NTILES - p;                 // tiles in row p
    int t0 = (q * 65) >> 2, t1 = ((q + 1) * 65) >> 2;

    const __nv_bfloat16* pb = g_proj + (size_t)batch * NROWS * DMEM;
    const float* Xb = X + (size_t)batch * NROWS * DMEM;
    float* outb = out + (size_t)batch * NROWS * DMEM;
    float* degb = g_deg + batch * NROWS;

    #define JOF(t) (((t) < n0) ? (p + (t)) : ((63 - p) + ((t) - n0)))
    #define IOF(t) (((t) < n0) ? p : (63 - p))

    int cur_i = IOF(t0);
    copy_tile16(smA, pb + (size_t)cur_i * 128 * DMEM, tid);
    copy_tile16(smB0, pb + (size_t)JOF(t0) * 128 * DMEM, tid);
    asm volatile("cp.async.commit_group;" ::: "memory");
    if (t0 + 1 < t1)
        copy_tile16(smB1, pb + (size_t)JOF(t0 + 1) * 128 * DMEM, tid);
    asm volatile("cp.async.commit_group;" ::: "memory");
    asm volatile("cp.async.wait_group 1;" ::: "memory");
    __syncthreads();

    uint32_t a[2][8][4];
    load_afrags(a, smA, wm, l);

    for (int t = t0; t < t1; t++) {
        if (IOF(t) != cur_i) {             // row crossing: reload A (once per CTA)
            cur_i = IOF(t);
            __syncthreads();
            copy_tile16(smA, pb + (size_t)cur_i * 128 * DMEM, tid);
            asm volatile("cp.async.commit_group;" ::: "memory");
            asm volatile("cp.async.wait_group 0;" ::: "memory");
            __syncthreads();
            load_afrags(a, smA, wm, l);
        }
        int it = cur_i, jt = JOF(t);
        bool diag = (it == jt);
        uint32_t smB = ((t - t0) & 1) ? smB1 : smB0;

        #pragma unroll 1
        for (int g = 0; g < 4; g++) {
            int n0c = wn * 64 + g * 16;
            float d[2][2][4];
            #pragma unroll
            for (int m = 0; m < 2; m++)
                #pragma unroll
                for (int h = 0; h < 2; h++)
                    #pragma unroll
                    for (int pp = 0; pp < 4; pp++) d[m][h][pp] = 0.f;

            #pragma unroll
            for (int k = 0; k < 8; k++) {
                int nn = n0c + (l & 7) + ((l & 16) ? 8 : 0);
                int chunk = k * 2 + ((l >> 3) & 1);
                uint32_t addr = smB + nn * 256 + ((chunk ^ (nn & 7)) << 4);
                uint32_t b0, b1, b2, b3;
                LDMATRIX_X4(b0, b1, b2, b3, addr);
                #pragma unroll
                for (int m = 0; m < 2; m++) {
                    MMA_BF16(d[m][0], a[m][k], b0, b1);
                    MMA_BF16(d[m][1], a[m][k], b2, b3);
                }
            }

            float vmax = d[0][0][0];
            #pragma unroll
            for (int m = 0; m < 2; m++)
                #pragma unroll
                for (int h = 0; h < 2; h++)
                    #pragma unroll
                    for (int pp = 0; pp < 4; pp++) vmax = fmaxf(vmax, d[m][h][pp]);
            unsigned warp_any = __ballot_sync(0xffffffffu, vmax > THRESH);

            if (warp_any) {   // rare: diagonal (self-sim, skipped) or a true hit
                #pragma unroll
                for (int m = 0; m < 2; m++)
                    #pragma unroll
                    for (int h = 0; h < 2; h++)
                        #pragma unroll
                        for (int pp = 0; pp < 4; pp++) {
                            unsigned msk = __ballot_sync(0xffffffffu, d[m][h][pp] > THRESH);
                            while (msk) {
                                int b = __ffs(msk) - 1; msk &= msk - 1;
                                int ib = it * 128 + wm * 32 + m * 16 + (b >> 2) + ((pp & 2) ? 8 : 0);
                                int jb = jt * 128 + n0c + h * 8 + ((b & 3) << 1) + (pp & 1);
                                if (ib != jb) {
                                    float4 xj = reinterpret_cast<const float4*>(Xb + (size_t)jb * DMEM)[l];
                                    float* oi = outb + (size_t)ib * DMEM + l * 4;
                                    atomicAdd(oi + 0, xj.x); atomicAdd(oi + 1, xj.y);
                                    atomicAdd(oi + 2, xj.z); atomicAdd(oi + 3, xj.w);
                                    if (l == 0) atomicAdd(&degb[ib], 1.0f);
                                    if (!diag) {   // symmetric partner (jb, ib)
                                        float4 xi = reinterpret_cast<const float4*>(Xb + (size_t)ib * DMEM)[l];
                                        float* oj = outb + (size_t)jb * DMEM + l * 4;
                                        atomicAdd(oj + 0, xi.x); atomicAdd(oj + 1, xi.y);
                                        atomicAdd(oj + 2, xi.z); atomicAdd(oj + 3, xi.w);
                                        if (l == 0) atomicAdd(&degb[jb], 1.0f);
                                    }
                                }
                            }
                        }
            }
        }

        __syncthreads();
        if (t + 2 < t1)
            copy_tile16(smB, pb + (size_t)JOF(t + 2) * 128 * DMEM, tid);
        asm volatile("cp.async.commit_group;" ::: "memory");
        asm volatile("cp.async.wait_group 1;" ::: "memory");
        __syncthreads();
    }
    #undef JOF
    #undef IOF
}

// ---------------------------------------------------------------------------
// Stage 3: out[i] *= 1/(1 + deg_hits[i])   (out already holds X[i] + hits)
// ---------------------------------------------------------------------------
__global__ void __launch_bounds__(256) fin_kernel(float* __restrict__ out) {
    size_t v = (size_t)blockIdx.x * 256 + threadIdx.x;
    int row = (int)(v >> 5);
    float inv = 1.0f / (1.0f + g_deg[row]);
    float4 o = reinterpret_cast<float4*>(out)[v];
    o.x *= inv; o.y *= inv; o.z *= inv; o.w *= inv;
    reinterpret_cast<float4*>(out)[v] = o;
}

// ---------------------------------------------------------------------------
extern "C" void kernel_launch(void* const* d_in, const int* in_sizes, int n_in,
                              void* d_out, int out_size) {
    (void)in_sizes; (void)n_in; (void)out_size;
    const float* X  = (const float*)d_in[0];
    const float* W  = (const float*)d_in[1];
    const float* Bv = (const float*)d_in[2];
    float* out = (float*)d_out;

    const int PROJ_SMEM = 65536 + 512;
    const int SIM_SMEM  = 3 * TILEB;     // 96 KB
    cudaFuncSetAttribute(proj_kernel, cudaFuncAttributeMaxDynamicSharedMemorySize, PROJ_SMEM);
    cudaFuncSetAttribute(sim_kernel,  cudaFuncAttributeMaxDynamicSharedMemorySize, SIM_SMEM);

    prep_kernel<<<2072, 256>>>(X, W, out);
    proj_kernel<<<(NBATCH * NROWS) / 128, 256, PROJ_SMEM>>>(Bv);
    sim_kernel<<<NBATCH * 32 * 4, 256, SIM_SMEM>>>(X, out);
    fin_kernel<<<(NBATCH * NROWS * DMEM / 4) / 256, 256>>>(out);
}